// round 17
// baseline (speedup 1.0000x reference)
#include <cuda_runtime.h>
#include <cstdint>

// DiagLinear fused via 8-CTA clusters + DSMEM epilogue exchange:
//   y[m, n*16+p] = sum_k x[m, p*256+k] * w[p, n, k] + bias[n*16+p]
// Cluster = 8 CTAs = partitions pg*8..pg*8+7 of one (m-tile, n-half).
// After the (unchanged, proven) TF32 mma.sync mainloop, CTAs exchange their
// output tiles through distributed shared memory so each CTA owns full 32B
// sectors of y (8 consecutive p for one n) -> direct coalesced stores,
// no scratch buffer, no permute kernel, no sector amplification.

#define P_PART 16
#define DIN    256
#define DOUT   256
#define KC     32
#define NCHUNK 8
#define STAGES 3

#define ABUF_BYTES 16384
#define BBUF_BYTES 16384
#define SMEM_B_OFF (STAGES * ABUF_BYTES)                // 49152
#define SMEM_BIAS  (SMEM_B_OFF + STAGES * BBUF_BYTES)   // 98304
#define GEMM_SMEM  (SMEM_BIAS + 640)                    // 98944

// Epilogue exchange buffer overlays the pipeline stages (dead after mainloop):
// buf[m 0..127][nl' 0..15][psrc 0..7], row stride 132 floats (pad: conflicts).
#define EX_ROW 132
// 128*132*4 = 67584 bytes < 98304 ok

__device__ float g_wtf[(size_t)P_PART * DOUT * DIN];    // rna W, 4MB

static __device__ __forceinline__ uint32_t smem_u32(const void* p) {
    uint32_t a;
    asm("{ .reg .u64 t; cvta.to.shared.u64 t, %1; cvt.u32.u64 %0, t; }" : "=r"(a) : "l"(p));
    return a;
}

static __device__ __forceinline__ uint32_t f2tf32(float v) {
    uint32_t u;
    asm("cvt.rna.tf32.f32 %0, %1;" : "=r"(u) : "f"(v));
    return u;
}

static __device__ __forceinline__ void cp_async16(uint32_t dst, const void* src) {
    asm volatile("cp.async.cg.shared.global [%0], [%1], 16;" :: "r"(dst), "l"(src));
}

static __device__ __forceinline__ void cluster_sync_() {
    asm volatile("barrier.cluster.arrive.aligned;" ::: "memory");
    asm volatile("barrier.cluster.wait.aligned;" ::: "memory");
}

__global__ __launch_bounds__(256)
void round_w(const float* __restrict__ w)
{
    int i = blockIdx.x * 256 + threadIdx.x;
    float4 v = reinterpret_cast<const float4*>(w)[i];
    float4 r;
    r.x = __uint_as_float(f2tf32(v.x));
    r.y = __uint_as_float(f2tf32(v.y));
    r.z = __uint_as_float(f2tf32(v.z));
    r.w = __uint_as_float(f2tf32(v.w));
    reinterpret_cast<float4*>(g_wtf)[i] = r;
}

__global__ __launch_bounds__(256, 2) __cluster_dims__(8, 1, 1)
void diag_gemm_cl(const float* __restrict__ x, const float* __restrict__ bias,
                  float* __restrict__ y)
{
    extern __shared__ char smem[];
    const int tid  = threadIdx.x;
    const int wid  = tid >> 5;
    const int lane = tid & 31;

    // grid.x = 32: [prank(8) | pg(1b) | nhalf(1b)]; cluster spans prank.
    const int prank = blockIdx.x & 7;          // cluster rank
    const int pg    = (blockIdx.x >> 3) & 1;   // partition group (p high bit)
    const int nhalf = blockIdx.x >> 4;
    const int p     = pg * 8 + prank;
    const int n0    = nhalf * 128;
    const int m0    = blockIdx.y * 128;

    const int warp_m = wid & 3;
    const int warp_n = wid >> 2;

    const float* xbase = x + (size_t)m0 * (P_PART * DIN) + (size_t)p * DIN;
    const float* wbase = g_wtf + (size_t)p * (DOUT * DIN) + (size_t)n0 * DIN;

    const uint32_t sbase = smem_u32(smem);

    {   // bias_s[i] = bias[(n0+i)*16 + p]
        float* bias_s = reinterpret_cast<float*>(smem + SMEM_BIAS);
        if (tid < 128) bias_s[tid] = bias[(n0 + tid) * P_PART + p];
    }

    const int g  = lane >> 3;
    const int l8 = lane & 7;
    const int rowA = warp_m * 32 + (g & 1) * 8 + l8;
    const int cA   = g >> 1;
    const int rowB = warp_n * 64 + (g >> 1) * 8 + l8;
    const int cB   = g & 1;

    const uint32_t aAddr0 = sbase + rowA * 128;
    const uint32_t bAddr0 = sbase + SMEM_B_OFF + rowB * 128;
    const int swA = rowA & 7, swB = rowB & 7;

#define ISSUE_STAGE(KCI, ST)                                                    \
    {                                                                           \
        const int kofs = (KCI) * KC;                                            \
        _Pragma("unroll")                                                       \
        for (int i = 0; i < 4; i++) {                                           \
            int idx = i * 256 + tid;                                            \
            int row = idx >> 3, q = idx & 7;                                    \
            uint32_t so = row * 128 + ((q ^ (row & 7)) << 4);                   \
            cp_async16(sbase + (ST) * ABUF_BYTES + so,                          \
                       xbase + (size_t)row * (P_PART * DIN) + kofs + q * 4);    \
            cp_async16(sbase + SMEM_B_OFF + (ST) * BBUF_BYTES + so,             \
                       wbase + (size_t)row * DIN + kofs + q * 4);               \
        }                                                                       \
        asm volatile("cp.async.commit_group;" ::: "memory");                    \
    }

    float acc[2][8][4];
#pragma unroll
    for (int mm = 0; mm < 2; mm++)
#pragma unroll
        for (int nn = 0; nn < 8; nn++)
#pragma unroll
            for (int c = 0; c < 4; c++) acc[mm][nn][c] = 0.0f;

#define LD_FRAGS(SET, ABASE, BBASE, KS)                                         \
    {                                                                           \
        const int cb = (KS) * 2;                                                \
        _Pragma("unroll")                                                       \
        for (int mm = 0; mm < 2; mm++) {                                        \
            uint32_t ad = (ABASE) + mm * 2048 + (((cb + cA) ^ swA) << 4);       \
            asm volatile(                                                       \
                "ldmatrix.sync.aligned.m8n8.x4.shared.b16 {%0,%1,%2,%3}, [%4];" \
                : "=r"(a[SET][mm][0]), "=r"(a[SET][mm][1]),                     \
                  "=r"(a[SET][mm][2]), "=r"(a[SET][mm][3])                      \
                : "r"(ad));                                                     \
        }                                                                       \
        _Pragma("unroll")                                                       \
        for (int q = 0; q < 4; q++) {                                           \
            uint32_t bd = (BBASE) + q * 2048 + (((cb + cB) ^ swB) << 4);        \
            asm volatile(                                                       \
                "ldmatrix.sync.aligned.m8n8.x4.shared.b16 {%0,%1,%2,%3}, [%4];" \
                : "=r"(b[SET][q][0]), "=r"(b[SET][q][1]),                       \
                  "=r"(b[SET][q][2]), "=r"(b[SET][q][3])                        \
                : "r"(bd));                                                     \
        }                                                                       \
    }

#define MMA_SET(SET)                                                            \
    _Pragma("unroll")                                                           \
    for (int mm = 0; mm < 2; mm++)                                              \
        _Pragma("unroll")                                                       \
        for (int nn = 0; nn < 8; nn++) {                                        \
            asm volatile(                                                       \
                "mma.sync.aligned.m16n8k8.row.col.f32.tf32.tf32.f32 "           \
                "{%0,%1,%2,%3}, {%4,%5,%6,%7}, {%8,%9}, {%0,%1,%2,%3};"         \
                : "+f"(acc[mm][nn][0]), "+f"(acc[mm][nn][1]),                   \
                  "+f"(acc[mm][nn][2]), "+f"(acc[mm][nn][3])                    \
                : "r"(a[SET][mm][0]), "r"(a[SET][mm][1]),                       \
                  "r"(a[SET][mm][2]), "r"(a[SET][mm][3]),                       \
                  "r"(b[SET][nn >> 1][(nn & 1) * 2]),                           \
                  "r"(b[SET][nn >> 1][(nn & 1) * 2 + 1]));                      \
        }

#define COMPUTE(BUF)                                                            \
    {                                                                           \
        const uint32_t abase = aAddr0 + (BUF) * ABUF_BYTES;                     \
        const uint32_t bbase = bAddr0 + (BUF) * BBUF_BYTES;                     \
        uint32_t a[2][2][4], b[2][4][4];                                        \
        LD_FRAGS(0, abase, bbase, 0);                                           \
        LD_FRAGS(1, abase, bbase, 1);                                           \
        MMA_SET(0);                                                             \
        LD_FRAGS(0, abase, bbase, 2);                                           \
        MMA_SET(1);                                                             \
        LD_FRAGS(1, abase, bbase, 3);                                           \
        MMA_SET(0);                                                             \
        MMA_SET(1);                                                             \
    }

    ISSUE_STAGE(0, 0);
    ISSUE_STAGE(1, 1);

#pragma unroll 1
    for (int kc = 0; kc < NCHUNK; kc++) {
        if (kc == NCHUNK - 1)
            asm volatile("cp.async.wait_group 0;" ::: "memory");   // race fix
        else
            asm volatile("cp.async.wait_group 1;" ::: "memory");
        __syncthreads();
        if (kc + 2 < NCHUNK) {
            const int st = (kc + 2) % 3;
            ISSUE_STAGE(kc + 2, st);
        }
        COMPUTE(kc % 3);
    }

    // ================= epilogue: DSMEM exchange =================
    __syncthreads();          // this CTA done reading pipeline smem
    cluster_sync_();          // all cluster CTAs done -> smem reusable as exbuf

    {
        const float* bias_s = reinterpret_cast<const float*>(smem + SMEM_BIAS);
        const int r0 = lane >> 2;
        const int c0 = (lane & 3) * 2;

        // peer smem bases for the 4 receiver ranks this warp targets
        uint32_t peer_base[4];
#pragma unroll
        for (int j = 0; j < 4; j++) {
            uint32_t peer = (uint32_t)(warp_n * 4 + j);
            asm("mapa.shared::cluster.u32 %0, %1, %2;"
                : "=r"(peer_base[j]) : "r"(sbase), "r"(peer));
        }

        // scatter: value (mr, nl) -> peer (nl>>4) at buf[mr][nl&15][prank]
#pragma unroll
        for (int mm = 0; mm < 2; mm++) {
            const int mr = warp_m * 32 + mm * 16 + r0;
#pragma unroll
            for (int nn = 0; nn < 8; nn++) {
                const int nl  = warp_n * 64 + nn * 8 + c0;
                const int nlp = nl & 15;
                const uint32_t pb = peer_base[nn >> 1];
                const float b0 = bias_s[nl], b1 = bias_s[nl + 1];
                const uint32_t o00 = (uint32_t)((mr * EX_ROW + nlp * 8 + prank) * 4);
                const uint32_t o10 = o00 + (uint32_t)(8 * EX_ROW * 4);
                asm volatile("st.shared::cluster.b32 [%0], %1;"
                             :: "r"(pb + o00),      "r"(__float_as_uint(acc[mm][nn][0] + b0)) : "memory");
                asm volatile("st.shared::cluster.b32 [%0], %1;"
                             :: "r"(pb + o00 + 32), "r"(__float_as_uint(acc[mm][nn][1] + b1)) : "memory");
                asm volatile("st.shared::cluster.b32 [%0], %1;"
                             :: "r"(pb + o10),      "r"(__float_as_uint(acc[mm][nn][2] + b0)) : "memory");
                asm volatile("st.shared::cluster.b32 [%0], %1;"
                             :: "r"(pb + o10 + 32), "r"(__float_as_uint(acc[mm][nn][3] + b1)) : "memory");
            }
        }
    }

    cluster_sync_();          // all stores delivered cluster-wide

    // ---- write y: this CTA owns n = n0 + prank*16 + nl', sectors p=pg*8..+7 ----
    {
        const float* exb = reinterpret_cast<const float*>(smem);
#pragma unroll
        for (int i = 0; i < 8; i++) {
            const int task = i * 256 + tid;       // 2048 = 128 m x 16 nl'
            const int m    = task >> 4;
            const int nlp  = task & 15;
            const float* s = exb + m * EX_ROW + nlp * 8;
            float4 v0 = *reinterpret_cast<const float4*>(s);
            float4 v1 = *reinterpret_cast<const float4*>(s + 4);
            float* dst = y + (size_t)(m0 + m) * (DOUT * P_PART)
                           + (size_t)(n0 + prank * 16 + nlp) * P_PART + pg * 8;
            *reinterpret_cast<float4*>(dst)     = v0;
            *reinterpret_cast<float4*>(dst + 4) = v1;
        }
    }
}

extern "C" void kernel_launch(void* const* d_in, const int* in_sizes, int n_in,
                              void* d_out, int out_size)
{
    const float* x    = (const float*)d_in[0];
    const float* w    = (const float*)d_in[1];
    const float* bias = (const float*)d_in[2];
    float* y = (float*)d_out;

    int M = in_sizes[0] / (P_PART * DIN);      // 16384

    cudaFuncSetAttribute(diag_gemm_cl,
                         cudaFuncAttributeMaxDynamicSharedMemorySize, GEMM_SMEM);

    round_w<<<(P_PART * DOUT * DIN) / 1024, 256>>>(w);

    cudaLaunchConfig_t cfg = {};
    cfg.gridDim         = dim3(32, M / 128);   // x: prank(8) * pg(2) * nhalf(2)
    cfg.blockDim        = dim3(256);
    cfg.dynamicSmemBytes = GEMM_SMEM;
    cudaLaunchAttribute attrs[1];
    attrs[0].id = cudaLaunchAttributeClusterDimension;
    attrs[0].val.clusterDim = {8, 1, 1};
    cfg.attrs    = attrs;
    cfg.numAttrs = 1;
    cudaLaunchKernelEx(&cfg, diag_gemm_cl, x, bias, y);
}